// round 1
// baseline (speedup 1.0000x reference)
#include <cuda_runtime.h>

// Problem constants
constexpr int HID = 1024;
constexpr int NH  = 16;
constexpr int HD  = 64;     // head dim
constexpr int B   = 2;
constexpr int S   = 2048;
constexpr int M   = B * S;  // 4096 rows for projection GEMMs

// Scratch: __device__ globals (allocation-free rule)
__device__ float g_q[(size_t)B * NH * S * HD];     // [B,H,S,D]
__device__ float g_k[(size_t)B * NH * S * HD];
__device__ float g_v[(size_t)B * NH * S * HD];
__device__ float g_attn[(size_t)B * S * HID];      // [B,S,HID]

// ---------------------------------------------------------------------------
// GEMM: C = A @ W^T + bias
//   A: [M, HID] row-major, W: [HID, HID] row-major (row n = output feature n)
//   DEST 0/1/2: write to g_q/g_k/g_v in [B,H,S,D] layout
//   DEST 3:     A is g_attn, write plain [M, HID] to Cout
// 128x128 tile, BK=16, 256 threads, 8x8 per-thread microtile, fp32 SIMT.
// ---------------------------------------------------------------------------
template <int DEST>
__global__ __launch_bounds__(256, 2)
void gemm_kernel(const float* __restrict__ Ain,
                 const float* __restrict__ W,
                 const float* __restrict__ bias,
                 float* __restrict__ Cout)
{
    constexpr int BM = 128, BN = 128, BK = 16;
    __shared__ float As[BK][BM + 4];
    __shared__ float Bs[BK][BN + 4];

    const float* A = (DEST == 3) ? g_attn : Ain;

    const int t  = threadIdx.x;
    const int tx = t & 15;
    const int ty = t >> 4;
    const int m0 = blockIdx.y * BM;
    const int n0 = blockIdx.x * BN;

    const int lrow = t >> 2;          // 0..63
    const int lcol = (t & 3) << 2;    // 0,4,8,12

    float acc[8][8];
#pragma unroll
    for (int i = 0; i < 8; i++)
#pragma unroll
        for (int j = 0; j < 8; j++) acc[i][j] = 0.f;

    for (int k0 = 0; k0 < HID; k0 += BK) {
#pragma unroll
        for (int it = 0; it < 2; it++) {
            const int r = lrow + it * 64;
            float4 av = *(const float4*)&A[(size_t)(m0 + r) * HID + k0 + lcol];
            As[lcol + 0][r] = av.x; As[lcol + 1][r] = av.y;
            As[lcol + 2][r] = av.z; As[lcol + 3][r] = av.w;
            float4 wv = *(const float4*)&W[(size_t)(n0 + r) * HID + k0 + lcol];
            Bs[lcol + 0][r] = wv.x; Bs[lcol + 1][r] = wv.y;
            Bs[lcol + 2][r] = wv.z; Bs[lcol + 3][r] = wv.w;
        }
        __syncthreads();

#pragma unroll
        for (int kk = 0; kk < BK; kk++) {
            float a[8], b[8];
            *(float4*)&a[0] = *(const float4*)&As[kk][ty * 8];
            *(float4*)&a[4] = *(const float4*)&As[kk][ty * 8 + 4];
            *(float4*)&b[0] = *(const float4*)&Bs[kk][tx * 8];
            *(float4*)&b[4] = *(const float4*)&Bs[kk][tx * 8 + 4];
#pragma unroll
            for (int i = 0; i < 8; i++)
#pragma unroll
                for (int j = 0; j < 8; j++)
                    acc[i][j] = fmaf(a[i], b[j], acc[i][j]);
        }
        __syncthreads();
    }

    // Epilogue
#pragma unroll
    for (int i = 0; i < 8; i++) {
        const int m = m0 + ty * 8 + i;
#pragma unroll
        for (int j = 0; j < 8; j++) {
            const int n = n0 + tx * 8 + j;
            float v = acc[i][j] + bias[n];
            if (DEST < 3) {
                // write to [B, H, S, D]
                const int bb = m >> 11;          // m / S   (S = 2048)
                const int ss = m & (S - 1);
                const int hh = n >> 6;           // n / 64
                const int dd = n & 63;
                float* C = (DEST == 0) ? g_q : (DEST == 1) ? g_k : g_v;
                C[(((size_t)(bb * NH + hh) * S + ss) << 6) + dd] = v;
            } else {
                Cout[(size_t)m * HID + n] = v;
            }
        }
    }
}

// ---------------------------------------------------------------------------
// Causal flash attention.
// grid: (S/64, B*NH), block: 256 threads.
// Per CTA: 64 query rows; iterate 64-row K/V tiles with k0 <= q0 (causal
// tile skipping); mask only the diagonal tile. Online softmax, 16-lane
// shuffle row reductions. P reuses the K smem buffer.
// Q is pre-scaled by 1/sqrt(D) = 0.125 at load.
// Output written to g_attn in [B, S, HID] layout.
// ---------------------------------------------------------------------------
constexpr int QS_STRIDE = 65;   // padded
constexpr int VS_STRIDE = 64;   // unpadded (keeps float4 alignment)
constexpr int ATTN_SMEM_FLOATS = 64 * QS_STRIDE * 2 + 64 * VS_STRIDE;
constexpr int ATTN_SMEM_BYTES  = ATTN_SMEM_FLOATS * 4;  // 49664

__global__ __launch_bounds__(256)
void attn_kernel()
{
    extern __shared__ float sm[];
    float* Qs  = sm;                          // [64][65]
    float* KPs = sm + 64 * QS_STRIDE;         // [64][65], K tile then P tile
    float* Vs  = sm + 2 * 64 * QS_STRIDE;     // [64][64]

    const int t  = threadIdx.x;
    const int tx = t & 15;
    const int ty = t >> 4;
    const int q0 = blockIdx.x * 64;
    const int bh = blockIdx.y;
    const int bb = bh >> 4;
    const int hh = bh & 15;

    const float* Qg = g_q + (size_t)bh * S * HD;
    const float* Kg = g_k + (size_t)bh * S * HD;
    const float* Vg = g_v + (size_t)bh * S * HD;

    // Load + scale Q tile (64x64)
#pragma unroll
    for (int l = 0; l < 4; l++) {
        const int fi = t + l * 256;           // float4 index 0..1023
        const int r  = fi >> 4;
        const int d  = (fi & 15) << 2;
        float4 v = *(const float4*)&Qg[(size_t)(q0 + r) * HD + d];
        float* dst = &Qs[r * QS_STRIDE + d];
        dst[0] = v.x * 0.125f; dst[1] = v.y * 0.125f;
        dst[2] = v.z * 0.125f; dst[3] = v.w * 0.125f;
    }

    float m_i[4], l_i[4], O[4][4];
#pragma unroll
    for (int i = 0; i < 4; i++) {
        m_i[i] = -1e30f; l_i[i] = 0.f;
#pragma unroll
        for (int j = 0; j < 4; j++) O[i][j] = 0.f;
    }

    for (int k0 = 0; k0 <= q0; k0 += 64) {
        __syncthreads();  // P (in KPs) from prev iter fully consumed; Q ready on iter 0

        // Load K and V tiles
#pragma unroll
        for (int l = 0; l < 4; l++) {
            const int fi = t + l * 256;
            const int r  = fi >> 4;
            const int d  = (fi & 15) << 2;
            float4 kv = *(const float4*)&Kg[(size_t)(k0 + r) * HD + d];
            float* kd = &KPs[r * QS_STRIDE + d];
            kd[0] = kv.x; kd[1] = kv.y; kd[2] = kv.z; kd[3] = kv.w;
            float4 vv = *(const float4*)&Vg[(size_t)(k0 + r) * HD + d];
            *(float4*)&Vs[r * VS_STRIDE + d] = vv;
        }
        __syncthreads();

        // S = Q @ K^T (Q already scaled)
        float s[4][4];
#pragma unroll
        for (int i = 0; i < 4; i++)
#pragma unroll
            for (int j = 0; j < 4; j++) s[i][j] = 0.f;

        for (int d = 0; d < 64; d++) {
            float a[4], b[4];
#pragma unroll
            for (int i = 0; i < 4; i++) a[i] = Qs[(ty * 4 + i) * QS_STRIDE + d];
#pragma unroll
            for (int j = 0; j < 4; j++) b[j] = KPs[(tx * 4 + j) * QS_STRIDE + d];
#pragma unroll
            for (int i = 0; i < 4; i++)
#pragma unroll
                for (int j = 0; j < 4; j++)
                    s[i][j] = fmaf(a[i], b[j], s[i][j]);
        }

        if (k0 == q0) {
            // diagonal tile: keep if row >= col
#pragma unroll
            for (int i = 0; i < 4; i++)
#pragma unroll
                for (int j = 0; j < 4; j++)
                    if (ty * 4 + i < tx * 4 + j) s[i][j] = -1e30f;
        }

        // Online softmax update
        float p[4][4], sc[4];
#pragma unroll
        for (int i = 0; i < 4; i++) {
            float mx = s[i][0];
#pragma unroll
            for (int j = 1; j < 4; j++) mx = fmaxf(mx, s[i][j]);
            // reduce max over the 16 tx lanes (xor within 16-lane groups)
            mx = fmaxf(mx, __shfl_xor_sync(0xffffffffu, mx, 8));
            mx = fmaxf(mx, __shfl_xor_sync(0xffffffffu, mx, 4));
            mx = fmaxf(mx, __shfl_xor_sync(0xffffffffu, mx, 2));
            mx = fmaxf(mx, __shfl_xor_sync(0xffffffffu, mx, 1));
            const float mn = fmaxf(m_i[i], mx);
            float sum = 0.f;
#pragma unroll
            for (int j = 0; j < 4; j++) {
                p[i][j] = __expf(s[i][j] - mn);
                sum += p[i][j];
            }
            sum += __shfl_xor_sync(0xffffffffu, sum, 8);
            sum += __shfl_xor_sync(0xffffffffu, sum, 4);
            sum += __shfl_xor_sync(0xffffffffu, sum, 2);
            sum += __shfl_xor_sync(0xffffffffu, sum, 1);
            sc[i]  = __expf(m_i[i] - mn);
            l_i[i] = l_i[i] * sc[i] + sum;
            m_i[i] = mn;
        }
#pragma unroll
        for (int i = 0; i < 4; i++)
#pragma unroll
            for (int j = 0; j < 4; j++) O[i][j] *= sc[i];

        __syncthreads();   // all threads done reading K tile
        // store P into KPs
#pragma unroll
        for (int i = 0; i < 4; i++)
#pragma unroll
            for (int j = 0; j < 4; j++)
                KPs[(ty * 4 + i) * QS_STRIDE + tx * 4 + j] = p[i][j];
        __syncthreads();

        // O += P @ V   (O cols = head dim slice tx*4..tx*4+3)
        for (int c = 0; c < 64; c++) {
            float pv[4];
#pragma unroll
            for (int i = 0; i < 4; i++) pv[i] = KPs[(ty * 4 + i) * QS_STRIDE + c];
            float4 v4 = *(const float4*)&Vs[c * VS_STRIDE + tx * 4];
            const float vv[4] = {v4.x, v4.y, v4.z, v4.w};
#pragma unroll
            for (int i = 0; i < 4; i++)
#pragma unroll
                for (int j = 0; j < 4; j++)
                    O[i][j] = fmaf(pv[i], vv[j], O[i][j]);
        }
    }

    // Finalize + write to g_attn in [B, S, HID] layout
#pragma unroll
    for (int i = 0; i < 4; i++) {
        const float inv_l = 1.f / l_i[i];
        const int srow = q0 + ty * 4 + i;
        float* dst = &g_attn[((size_t)bb * S + srow) * HID + hh * 64 + tx * 4];
#pragma unroll
        for (int j = 0; j < 4; j++) dst[j] = O[i][j] * inv_l;
    }
}

// ---------------------------------------------------------------------------
// Launch: 3 QKV GEMMs -> attention -> output GEMM
// ---------------------------------------------------------------------------
extern "C" void kernel_launch(void* const* d_in, const int* in_sizes, int n_in,
                              void* d_out, int out_size)
{
    const float* x  = (const float*)d_in[0];
    const float* Wq = (const float*)d_in[1];
    const float* bq = (const float*)d_in[2];
    const float* Wk = (const float*)d_in[3];
    const float* bk = (const float*)d_in[4];
    const float* Wv = (const float*)d_in[5];
    const float* bv = (const float*)d_in[6];
    const float* Wo = (const float*)d_in[7];
    const float* bo = (const float*)d_in[8];
    float* out = (float*)d_out;

    cudaFuncSetAttribute(attn_kernel,
                         cudaFuncAttributeMaxDynamicSharedMemorySize,
                         ATTN_SMEM_BYTES);

    dim3 gg(HID / 128, M / 128);   // (8, 32)
    gemm_kernel<0><<<gg, 256>>>(x, Wq, bq, nullptr);
    gemm_kernel<1><<<gg, 256>>>(x, Wk, bk, nullptr);
    gemm_kernel<2><<<gg, 256>>>(x, Wv, bv, nullptr);

    attn_kernel<<<dim3(S / 64, B * NH), 256, ATTN_SMEM_BYTES>>>();

    gemm_kernel<3><<<gg, 256>>>(nullptr, Wo, bo, out);
}

// round 3
// speedup vs baseline: 1.5467x; 1.5467x over previous
#include <cuda_runtime.h>
#include <cuda_bf16.h>
#include <cstdint>

// Problem constants
constexpr int HID = 1024;
constexpr int NH  = 16;
constexpr int HD  = 64;     // head dim
constexpr int B   = 2;
constexpr int S   = 2048;
constexpr int M   = B * S;  // 4096 rows for projection GEMMs

// Scratch: __device__ globals (allocation-free rule)
__device__ float g_q[(size_t)B * NH * S * HD];     // [B,H,S,D]
__device__ float g_k[(size_t)B * NH * S * HD];
__device__ float g_v[(size_t)B * NH * S * HD];
__device__ float g_attn[(size_t)B * S * HID];      // [B,S,HID]

// ---------------------------------------------------------------------------
// mma.sync / ldmatrix helpers (base sm_103-compatible ISA)
// ---------------------------------------------------------------------------
__device__ __forceinline__ uint32_t smem_u32(const void* p) {
    uint32_t a;
    asm("{ .reg .u64 t; cvta.to.shared.u64 t, %1; cvt.u32.u64 %0, t; }"
        : "=r"(a) : "l"(p));
    return a;
}

__device__ __forceinline__ void ldsm_x4(uint32_t (&r)[4], uint32_t addr) {
    asm volatile("ldmatrix.sync.aligned.m8n8.x4.shared.b16 {%0,%1,%2,%3}, [%4];"
                 : "=r"(r[0]), "=r"(r[1]), "=r"(r[2]), "=r"(r[3]) : "r"(addr));
}

__device__ __forceinline__ void mma_bf16(float (&d)[4], const uint32_t (&a)[4],
                                         uint32_t b0, uint32_t b1) {
    asm volatile(
        "mma.sync.aligned.m16n8k16.row.col.f32.bf16.bf16.f32 "
        "{%0,%1,%2,%3}, {%4,%5,%6,%7}, {%8,%9}, {%0,%1,%2,%3};"
        : "+f"(d[0]), "+f"(d[1]), "+f"(d[2]), "+f"(d[3])
        : "r"(a[0]), "r"(a[1]), "r"(a[2]), "r"(a[3]), "r"(b0), "r"(b1));
}

__device__ __forceinline__ uint32_t pack2bf16(float a, float b) {
    __nv_bfloat162 h = __floats2bfloat162_rn(a, b);
    return *reinterpret_cast<uint32_t*>(&h);
}

// ---------------------------------------------------------------------------
// bf16-split tensor-core GEMM:  C = A @ W^T + bias  (fp32 in/out)
// A: [M,1024] row-major, W: [1024,1024] row-major (row n = output feature n).
// f32 operands split on-the-fly: v = hi(bf16) + lo(bf16), 3 MMAs per K16
// (hi*hi + hi*lo + lo*hi) accumulated in fp32 -> ~1e-5 rel err.
// CTA: 128x128 tile, BK=32, 256 threads. Warp grid 2(M)x4(N); warp tile
// 64x32 = 4 m16-tiles x 4 n8-tiles.
//   DEST 0/1/2: scatter into g_q/g_k/g_v in [B,H,S,D] layout
//   DEST 3:     A = g_attn, write [M,HID] to Cout
// ---------------------------------------------------------------------------
constexpr int AST = 40;   // padded bf16 row stride (80B: 16B-aligned, conflict-free)

template <int DEST>
__global__ __launch_bounds__(256, 2)
void gemm_mma_kernel(const float* __restrict__ Ain,
                     const float* __restrict__ W,
                     const float* __restrict__ bias,
                     float* __restrict__ Cout)
{
    __shared__ __align__(16) __nv_bfloat16 Ahi[128][AST];
    __shared__ __align__(16) __nv_bfloat16 Alo[128][AST];
    __shared__ __align__(16) __nv_bfloat16 Bhi[128][AST];
    __shared__ __align__(16) __nv_bfloat16 Blo[128][AST];

    const float* A = (DEST == 3) ? g_attn : Ain;

    const int t      = threadIdx.x;
    const int lane   = t & 31;
    const int wid    = t >> 5;
    const int warp_m = wid >> 2;      // 0..1 -> 64 rows each
    const int warp_n = wid & 3;       // 0..3 -> 32 cols each
    const int m0 = blockIdx.y * 128;
    const int n0 = blockIdx.x * 128;

    const uint32_t ahi_b = smem_u32(&Ahi[0][0]);
    const uint32_t alo_b = smem_u32(&Alo[0][0]);
    const uint32_t bhi_b = smem_u32(&Bhi[0][0]);
    const uint32_t blo_b = smem_u32(&Blo[0][0]);

    // ldmatrix lane addressing (byte offsets within a tile's smem region)
    // A (16x16): lanes 0-15 -> rows 0-15 k0-7; lanes 16-31 -> rows 0-15 k8-15
    const int a_row = lane & 15;
    const int a_kb  = (lane >> 4) * 16;
    // B (two n8k16 tiles): lane l -> n = (l&7) + (l>>4)*8 ; kbyte = ((l>>3)&1)*16
    const int b_row = (lane & 7) + ((lane >> 4) << 3);
    const int b_kb  = ((lane >> 3) & 1) * 16;

    float acc[4][4][4];
#pragma unroll
    for (int mt = 0; mt < 4; mt++)
#pragma unroll
        for (int nt = 0; nt < 4; nt++)
#pragma unroll
            for (int r = 0; r < 4; r++) acc[mt][nt][r] = 0.f;

    for (int k0 = 0; k0 < HID; k0 += 32) {
        // ---- load + split 128x32 f32 tiles of A and W into bf16 hi/lo ----
#pragma unroll
        for (int it = 0; it < 4; it++) {
            const int i  = t + it * 256;          // 0..1023
            const int r  = i >> 3;                // row 0..127
            const int c4 = (i & 7) << 2;          // col 0,4,..,28
            const int eoff = r * AST + c4;

            float4 av = *(const float4*)&A[(size_t)(m0 + r) * HID + k0 + c4];
            float hx = __bfloat162float(__float2bfloat16(av.x));
            float hy = __bfloat162float(__float2bfloat16(av.y));
            float hz = __bfloat162float(__float2bfloat16(av.z));
            float hw = __bfloat162float(__float2bfloat16(av.w));
            *(uint2*)&Ahi[0][eoff] =
                make_uint2(pack2bf16(av.x, av.y), pack2bf16(av.z, av.w));
            *(uint2*)&Alo[0][eoff] =
                make_uint2(pack2bf16(av.x - hx, av.y - hy),
                           pack2bf16(av.z - hz, av.w - hw));

            float4 wv = *(const float4*)&W[(size_t)(n0 + r) * HID + k0 + c4];
            hx = __bfloat162float(__float2bfloat16(wv.x));
            hy = __bfloat162float(__float2bfloat16(wv.y));
            hz = __bfloat162float(__float2bfloat16(wv.z));
            hw = __bfloat162float(__float2bfloat16(wv.w));
            *(uint2*)&Bhi[0][eoff] =
                make_uint2(pack2bf16(wv.x, wv.y), pack2bf16(wv.z, wv.w));
            *(uint2*)&Blo[0][eoff] =
                make_uint2(pack2bf16(wv.x - hx, wv.y - hy),
                           pack2bf16(wv.z - hz, wv.w - hw));
        }
        __syncthreads();

        // ---- 2 K16 steps of MMAs ----
#pragma unroll
        for (int ks = 0; ks < 2; ks++) {
            const int ksb = ks * 32;   // byte offset of this k16 step

            uint32_t a_hi[4][4], a_lo[4][4];
#pragma unroll
            for (int mt = 0; mt < 4; mt++) {
                const uint32_t ro =
                    (uint32_t)((warp_m * 64 + mt * 16 + a_row) * (AST * 2)
                               + ksb + a_kb);
                ldsm_x4(a_hi[mt], ahi_b + ro);
                ldsm_x4(a_lo[mt], alo_b + ro);
            }
            uint32_t b_hi[2][4], b_lo[2][4];
#pragma unroll
            for (int bt = 0; bt < 2; bt++) {
                const uint32_t ro =
                    (uint32_t)((warp_n * 32 + bt * 16 + b_row) * (AST * 2)
                               + ksb + b_kb);
                ldsm_x4(b_hi[bt], bhi_b + ro);
                ldsm_x4(b_lo[bt], blo_b + ro);
            }

#pragma unroll
            for (int mt = 0; mt < 4; mt++)
#pragma unroll
                for (int nt = 0; nt < 4; nt++) {
                    const int bt = nt >> 1;
                    const int hf = (nt & 1) * 2;
                    mma_bf16(acc[mt][nt], a_hi[mt], b_hi[bt][hf], b_hi[bt][hf + 1]);
                    mma_bf16(acc[mt][nt], a_hi[mt], b_lo[bt][hf], b_lo[bt][hf + 1]);
                    mma_bf16(acc[mt][nt], a_lo[mt], b_hi[bt][hf], b_hi[bt][hf + 1]);
                }
        }
        __syncthreads();
    }

    // ---- epilogue: fragment -> global (+bias) ----
    const int fr = lane >> 2;          // 0..7
    const int fc = (lane & 3) * 2;     // 0,2,4,6
#pragma unroll
    for (int mt = 0; mt < 4; mt++)
#pragma unroll
        for (int nt = 0; nt < 4; nt++) {
            const int n = n0 + warp_n * 32 + nt * 8 + fc;
            const float2 b2 = *(const float2*)&bias[n];
#pragma unroll
            for (int p = 0; p < 2; p++) {
                const int m = m0 + warp_m * 64 + mt * 16 + fr + p * 8;
                float2 v;
                v.x = acc[mt][nt][p * 2 + 0] + b2.x;
                v.y = acc[mt][nt][p * 2 + 1] + b2.y;
                if (DEST < 3) {
                    const int bb = m >> 11;
                    const int ss = m & (S - 1);
                    const int hh = n >> 6;
                    const int dd = n & 63;
                    float* C = (DEST == 0) ? g_q : (DEST == 1) ? g_k : g_v;
                    *(float2*)&C[(((size_t)(bb * NH + hh) * S + ss) << 6) + dd] = v;
                } else {
                    *(float2*)&Cout[(size_t)m * HID + n] = v;
                }
            }
        }
}

// ---------------------------------------------------------------------------
// Causal flash attention (unchanged from R1 — known good; R4 target).
// ---------------------------------------------------------------------------
constexpr int QS_STRIDE = 65;
constexpr int VS_STRIDE = 64;
constexpr int ATTN_SMEM_FLOATS = 64 * QS_STRIDE * 2 + 64 * VS_STRIDE;
constexpr int ATTN_SMEM_BYTES  = ATTN_SMEM_FLOATS * 4;

__global__ __launch_bounds__(256)
void attn_kernel()
{
    extern __shared__ float sm[];
    float* Qs  = sm;
    float* KPs = sm + 64 * QS_STRIDE;
    float* Vs  = sm + 2 * 64 * QS_STRIDE;

    const int t  = threadIdx.x;
    const int tx = t & 15;
    const int ty = t >> 4;
    const int q0 = blockIdx.x * 64;
    const int bh = blockIdx.y;
    const int bb = bh >> 4;
    const int hh = bh & 15;

    const float* Qg = g_q + (size_t)bh * S * HD;
    const float* Kg = g_k + (size_t)bh * S * HD;
    const float* Vg = g_v + (size_t)bh * S * HD;

#pragma unroll
    for (int l = 0; l < 4; l++) {
        const int fi = t + l * 256;
        const int r  = fi >> 4;
        const int d  = (fi & 15) << 2;
        float4 v = *(const float4*)&Qg[(size_t)(q0 + r) * HD + d];
        float* dst = &Qs[r * QS_STRIDE + d];
        dst[0] = v.x * 0.125f; dst[1] = v.y * 0.125f;
        dst[2] = v.z * 0.125f; dst[3] = v.w * 0.125f;
    }

    float m_i[4], l_i[4], O[4][4];
#pragma unroll
    for (int i = 0; i < 4; i++) {
        m_i[i] = -1e30f; l_i[i] = 0.f;
#pragma unroll
        for (int j = 0; j < 4; j++) O[i][j] = 0.f;
    }

    for (int k0 = 0; k0 <= q0; k0 += 64) {
        __syncthreads();

#pragma unroll
        for (int l = 0; l < 4; l++) {
            const int fi = t + l * 256;
            const int r  = fi >> 4;
            const int d  = (fi & 15) << 2;
            float4 kv = *(const float4*)&Kg[(size_t)(k0 + r) * HD + d];
            float* kd = &KPs[r * QS_STRIDE + d];
            kd[0] = kv.x; kd[1] = kv.y; kd[2] = kv.z; kd[3] = kv.w;
            float4 vv = *(const float4*)&Vg[(size_t)(k0 + r) * HD + d];
            *(float4*)&Vs[r * VS_STRIDE + d] = vv;
        }
        __syncthreads();

        float s[4][4];
#pragma unroll
        for (int i = 0; i < 4; i++)
#pragma unroll
            for (int j = 0; j < 4; j++) s[i][j] = 0.f;

        for (int d = 0; d < 64; d++) {
            float a[4], b[4];
#pragma unroll
            for (int i = 0; i < 4; i++) a[i] = Qs[(ty * 4 + i) * QS_STRIDE + d];
#pragma unroll
            for (int j = 0; j < 4; j++) b[j] = KPs[(tx * 4 + j) * QS_STRIDE + d];
#pragma unroll
            for (int i = 0; i < 4; i++)
#pragma unroll
                for (int j = 0; j < 4; j++)
                    s[i][j] = fmaf(a[i], b[j], s[i][j]);
        }

        if (k0 == q0) {
#pragma unroll
            for (int i = 0; i < 4; i++)
#pragma unroll
                for (int j = 0; j < 4; j++)
                    if (ty * 4 + i < tx * 4 + j) s[i][j] = -1e30f;
        }

        float p[4][4], sc[4];
#pragma unroll
        for (int i = 0; i < 4; i++) {
            float mx = s[i][0];
#pragma unroll
            for (int j = 1; j < 4; j++) mx = fmaxf(mx, s[i][j]);
            mx = fmaxf(mx, __shfl_xor_sync(0xffffffffu, mx, 8));
            mx = fmaxf(mx, __shfl_xor_sync(0xffffffffu, mx, 4));
            mx = fmaxf(mx, __shfl_xor_sync(0xffffffffu, mx, 2));
            mx = fmaxf(mx, __shfl_xor_sync(0xffffffffu, mx, 1));
            const float mn = fmaxf(m_i[i], mx);
            float sum = 0.f;
#pragma unroll
            for (int j = 0; j < 4; j++) {
                p[i][j] = __expf(s[i][j] - mn);
                sum += p[i][j];
            }
            sum += __shfl_xor_sync(0xffffffffu, sum, 8);
            sum += __shfl_xor_sync(0xffffffffu, sum, 4);
            sum += __shfl_xor_sync(0xffffffffu, sum, 2);
            sum += __shfl_xor_sync(0xffffffffu, sum, 1);
            sc[i]  = __expf(m_i[i] - mn);
            l_i[i] = l_i[i] * sc[i] + sum;
            m_i[i] = mn;
        }
#pragma unroll
        for (int i = 0; i < 4; i++)
#pragma unroll
            for (int j = 0; j < 4; j++) O[i][j] *= sc[i];

        __syncthreads();
#pragma unroll
        for (int i = 0; i < 4; i++)
#pragma unroll
            for (int j = 0; j < 4; j++)
                KPs[(ty * 4 + i) * QS_STRIDE + tx * 4 + j] = p[i][j];
        __syncthreads();

        for (int c = 0; c < 64; c++) {
            float pv[4];
#pragma unroll
            for (int i = 0; i < 4; i++) pv[i] = KPs[(ty * 4 + i) * QS_STRIDE + c];
            float4 v4 = *(const float4*)&Vs[c * VS_STRIDE + tx * 4];
            const float vv[4] = {v4.x, v4.y, v4.z, v4.w};
#pragma unroll
            for (int i = 0; i < 4; i++)
#pragma unroll
                for (int j = 0; j < 4; j++)
                    O[i][j] = fmaf(pv[i], vv[j], O[i][j]);
        }
    }

#pragma unroll
    for (int i = 0; i < 4; i++) {
        const float inv_l = 1.f / l_i[i];
        const int srow = q0 + ty * 4 + i;
        float* dst = &g_attn[((size_t)bb * S + srow) * HID + hh * 64 + tx * 4];
#pragma unroll
        for (int j = 0; j < 4; j++) dst[j] = O[i][j] * inv_l;
    }
}

// ---------------------------------------------------------------------------
// Launch: 3 QKV GEMMs -> attention -> output GEMM
// ---------------------------------------------------------------------------
extern "C" void kernel_launch(void* const* d_in, const int* in_sizes, int n_in,
                              void* d_out, int out_size)
{
    const float* x  = (const float*)d_in[0];
    const float* Wq = (const float*)d_in[1];
    const float* bq = (const float*)d_in[2];
    const float* Wk = (const float*)d_in[3];
    const float* bk = (const float*)d_in[4];
    const float* Wv = (const float*)d_in[5];
    const float* bv = (const float*)d_in[6];
    const float* Wo = (const float*)d_in[7];
    const float* bo = (const float*)d_in[8];
    float* out = (float*)d_out;

    cudaFuncSetAttribute(attn_kernel,
                         cudaFuncAttributeMaxDynamicSharedMemorySize,
                         ATTN_SMEM_BYTES);

    dim3 gg(HID / 128, M / 128);   // (8, 32)
    gemm_mma_kernel<0><<<gg, 256>>>(x, Wq, bq, nullptr);
    gemm_mma_kernel<1><<<gg, 256>>>(x, Wk, bk, nullptr);
    gemm_mma_kernel<2><<<gg, 256>>>(x, Wv, bv, nullptr);

    attn_kernel<<<dim3(S / 64, B * NH), 256, ATTN_SMEM_BYTES>>>();

    gemm_mma_kernel<3><<<gg, 256>>>(nullptr, Wo, bo, out);
}

// round 6
// speedup vs baseline: 2.6245x; 1.6968x over previous
#include <cuda_runtime.h>
#include <cuda_bf16.h>
#include <cstdint>

// Problem constants
constexpr int HID = 1024;
constexpr int NH  = 16;
constexpr int HD  = 64;     // head dim
constexpr int B   = 2;
constexpr int S   = 2048;
constexpr int M   = B * S;  // 4096 rows for projection GEMMs

// Scratch: __device__ globals (allocation-free rule)
__device__ float g_q[(size_t)B * NH * S * HD];     // [B,H,S,D]
__device__ float g_k[(size_t)B * NH * S * HD];
__device__ float g_v[(size_t)B * NH * S * HD];
__device__ float g_attn[(size_t)B * S * HID];      // [B,S,HID]

// ---------------------------------------------------------------------------
// mma.sync / ldmatrix helpers (base sm_103-compatible ISA)
// ---------------------------------------------------------------------------
__device__ __forceinline__ uint32_t smem_u32(const void* p) {
    uint32_t a;
    asm("{ .reg .u64 t; cvta.to.shared.u64 t, %1; cvt.u32.u64 %0, t; }"
        : "=r"(a) : "l"(p));
    return a;
}

__device__ __forceinline__ void ldsm_x4(uint32_t (&r)[4], uint32_t addr) {
    asm volatile("ldmatrix.sync.aligned.m8n8.x4.shared.b16 {%0,%1,%2,%3}, [%4];"
                 : "=r"(r[0]), "=r"(r[1]), "=r"(r[2]), "=r"(r[3]) : "r"(addr));
}

__device__ __forceinline__ void ldsm_x4_t(uint32_t (&r)[4], uint32_t addr) {
    asm volatile("ldmatrix.sync.aligned.m8n8.x4.trans.shared.b16 {%0,%1,%2,%3}, [%4];"
                 : "=r"(r[0]), "=r"(r[1]), "=r"(r[2]), "=r"(r[3]) : "r"(addr));
}

__device__ __forceinline__ void mma_bf16(float (&d)[4], const uint32_t (&a)[4],
                                         uint32_t b0, uint32_t b1) {
    asm volatile(
        "mma.sync.aligned.m16n8k16.row.col.f32.bf16.bf16.f32 "
        "{%0,%1,%2,%3}, {%4,%5,%6,%7}, {%8,%9}, {%0,%1,%2,%3};"
        : "+f"(d[0]), "+f"(d[1]), "+f"(d[2]), "+f"(d[3])
        : "r"(a[0]), "r"(a[1]), "r"(a[2]), "r"(a[3]), "r"(b0), "r"(b1));
}

__device__ __forceinline__ uint32_t pack2bf16(float a, float b) {
    __nv_bfloat162 h = __floats2bfloat162_rn(a, b);
    return *reinterpret_cast<uint32_t*>(&h);
}

__device__ __forceinline__ float bf16round(float x) {
    return __bfloat162float(__float2bfloat16(x));
}

// ---------------------------------------------------------------------------
// bf16-split tensor-core GEMM:  C = A @ W^T + bias  (fp32 in/out)
// (unchanged from R3 — verified)
// ---------------------------------------------------------------------------
constexpr int AST = 40;   // padded bf16 row stride (BK=32 + 8 pad)

template <int DEST>
__global__ __launch_bounds__(256, 2)
void gemm_mma_kernel(const float* __restrict__ Ain,
                     const float* __restrict__ W,
                     const float* __restrict__ bias,
                     float* __restrict__ Cout)
{
    __shared__ __align__(16) __nv_bfloat16 Ahi[128][AST];
    __shared__ __align__(16) __nv_bfloat16 Alo[128][AST];
    __shared__ __align__(16) __nv_bfloat16 Bhi[128][AST];
    __shared__ __align__(16) __nv_bfloat16 Blo[128][AST];

    const float* A = (DEST == 3) ? g_attn : Ain;

    const int t      = threadIdx.x;
    const int lane   = t & 31;
    const int wid    = t >> 5;
    const int warp_m = wid >> 2;
    const int warp_n = wid & 3;
    const int m0 = blockIdx.y * 128;
    const int n0 = blockIdx.x * 128;

    const uint32_t ahi_b = smem_u32(&Ahi[0][0]);
    const uint32_t alo_b = smem_u32(&Alo[0][0]);
    const uint32_t bhi_b = smem_u32(&Bhi[0][0]);
    const uint32_t blo_b = smem_u32(&Blo[0][0]);

    const int a_row = lane & 15;
    const int a_kb  = (lane >> 4) * 16;
    const int b_row = (lane & 7) + ((lane >> 4) << 3);
    const int b_kb  = ((lane >> 3) & 1) * 16;

    float acc[4][4][4];
#pragma unroll
    for (int mt = 0; mt < 4; mt++)
#pragma unroll
        for (int nt = 0; nt < 4; nt++)
#pragma unroll
            for (int r = 0; r < 4; r++) acc[mt][nt][r] = 0.f;

    for (int k0 = 0; k0 < HID; k0 += 32) {
#pragma unroll
        for (int it = 0; it < 4; it++) {
            const int i  = t + it * 256;
            const int r  = i >> 3;
            const int c4 = (i & 7) << 2;
            const int eoff = r * AST + c4;

            float4 av = *(const float4*)&A[(size_t)(m0 + r) * HID + k0 + c4];
            float hx = bf16round(av.x), hy = bf16round(av.y);
            float hz = bf16round(av.z), hw = bf16round(av.w);
            *(uint2*)&Ahi[0][eoff] =
                make_uint2(pack2bf16(av.x, av.y), pack2bf16(av.z, av.w));
            *(uint2*)&Alo[0][eoff] =
                make_uint2(pack2bf16(av.x - hx, av.y - hy),
                           pack2bf16(av.z - hz, av.w - hw));

            float4 wv = *(const float4*)&W[(size_t)(n0 + r) * HID + k0 + c4];
            hx = bf16round(wv.x); hy = bf16round(wv.y);
            hz = bf16round(wv.z); hw = bf16round(wv.w);
            *(uint2*)&Bhi[0][eoff] =
                make_uint2(pack2bf16(wv.x, wv.y), pack2bf16(wv.z, wv.w));
            *(uint2*)&Blo[0][eoff] =
                make_uint2(pack2bf16(wv.x - hx, wv.y - hy),
                           pack2bf16(wv.z - hz, wv.w - hw));
        }
        __syncthreads();

#pragma unroll
        for (int ks = 0; ks < 2; ks++) {
            const int ksb = ks * 32;

            uint32_t a_hi[4][4], a_lo[4][4];
#pragma unroll
            for (int mt = 0; mt < 4; mt++) {
                const uint32_t ro =
                    (uint32_t)((warp_m * 64 + mt * 16 + a_row) * (AST * 2)
                               + ksb + a_kb);
                ldsm_x4(a_hi[mt], ahi_b + ro);
                ldsm_x4(a_lo[mt], alo_b + ro);
            }
            uint32_t b_hi[2][4], b_lo[2][4];
#pragma unroll
            for (int bt = 0; bt < 2; bt++) {
                const uint32_t ro =
                    (uint32_t)((warp_n * 32 + bt * 16 + b_row) * (AST * 2)
                               + ksb + b_kb);
                ldsm_x4(b_hi[bt], bhi_b + ro);
                ldsm_x4(b_lo[bt], blo_b + ro);
            }

#pragma unroll
            for (int mt = 0; mt < 4; mt++)
#pragma unroll
                for (int nt = 0; nt < 4; nt++) {
                    const int bt = nt >> 1;
                    const int hf = (nt & 1) * 2;
                    mma_bf16(acc[mt][nt], a_hi[mt], b_hi[bt][hf], b_hi[bt][hf + 1]);
                    mma_bf16(acc[mt][nt], a_hi[mt], b_lo[bt][hf], b_lo[bt][hf + 1]);
                    mma_bf16(acc[mt][nt], a_lo[mt], b_hi[bt][hf], b_hi[bt][hf + 1]);
                }
        }
        __syncthreads();
    }

    const int fr = lane >> 2;
    const int fc = (lane & 3) * 2;
#pragma unroll
    for (int mt = 0; mt < 4; mt++)
#pragma unroll
        for (int nt = 0; nt < 4; nt++) {
            const int n = n0 + warp_n * 32 + nt * 8 + fc;
            const float2 b2 = *(const float2*)&bias[n];
#pragma unroll
            for (int p = 0; p < 2; p++) {
                const int m = m0 + warp_m * 64 + mt * 16 + fr + p * 8;
                float2 v;
                v.x = acc[mt][nt][p * 2 + 0] + b2.x;
                v.y = acc[mt][nt][p * 2 + 1] + b2.y;
                if (DEST < 3) {
                    const int bb = m >> 11;
                    const int ss = m & (S - 1);
                    const int hh = n >> 6;
                    const int dd = n & 63;
                    float* C = (DEST == 0) ? g_q : (DEST == 1) ? g_k : g_v;
                    *(float2*)&C[(((size_t)(bb * NH + hh) * S + ss) << 6) + dd] = v;
                } else {
                    *(float2*)&Cout[(size_t)m * HID + n] = v;
                }
            }
        }
}

// ---------------------------------------------------------------------------
// Tensor-core causal flash attention (bf16-split mma.sync).
// CTA: 128 q rows, 8 warps (16 rows each); K/V tiles of 64 keys.
// grid: (S/128, B*NH), 256 threads.
// KST = 72: rows are 64 wide (head/key dim) + 8 pad  -> 144B row stride,
// 16B-aligned, consecutive rows hit distinct 16B bank groups (conflict-free).
// ---------------------------------------------------------------------------
constexpr int KST = 72;

__global__ __launch_bounds__(256)
void attn_mma_kernel()
{
    // one contiguous buffer: [Khi | Klo | Vhi | Vlo], each 64*KST bf16.
    // During Q staging: Qhi = rows 0..127 over (Khi,Klo), Qlo over (Vhi,Vlo).
    __shared__ __align__(16) __nv_bfloat16 sb[4 * 64 * KST];   // 36864 B

    const int t    = threadIdx.x;
    const int lane = t & 31;
    const int w    = t >> 5;
    const int q0   = (gridDim.x - 1 - blockIdx.x) * 128;  // longest CTAs first
    const int bh   = blockIdx.y;
    const int bb   = bh >> 4;
    const int hh   = bh & 15;

    const float* Qg = g_q + (size_t)bh * S * HD;
    const float* Kg = g_k + (size_t)bh * S * HD;
    const float* Vg = g_v + (size_t)bh * S * HD;

    const uint32_t sb_b  = smem_u32(sb);
    const uint32_t khi_b = sb_b;
    const uint32_t klo_b = sb_b + 64 * KST * 2;
    const uint32_t vhi_b = sb_b + 2 * 64 * KST * 2;
    const uint32_t vlo_b = sb_b + 3 * 64 * KST * 2;

    // ---- stage Q (scaled by 0.125), split hi/lo ----
    __nv_bfloat16* Qhi = sb;                 // 128 rows
    __nv_bfloat16* Qlo = sb + 2 * 64 * KST;  // 128 rows
#pragma unroll
    for (int it = 0; it < 8; it++) {
        const int i  = t + it * 256;      // 0..2047 float4
        const int r  = i >> 4;
        const int c4 = (i & 15) << 2;
        float4 v = *(const float4*)&Qg[(size_t)(q0 + r) * HD + c4];
        v.x *= 0.125f; v.y *= 0.125f; v.z *= 0.125f; v.w *= 0.125f;
        const float hx = bf16round(v.x), hy = bf16round(v.y);
        const float hz = bf16round(v.z), hw = bf16round(v.w);
        *(uint2*)&Qhi[r * KST + c4] =
            make_uint2(pack2bf16(v.x, v.y), pack2bf16(v.z, v.w));
        *(uint2*)&Qlo[r * KST + c4] =
            make_uint2(pack2bf16(v.x - hx, v.y - hy),
                       pack2bf16(v.z - hz, v.w - hw));
    }
    __syncthreads();

    // ---- load Q fragments to registers (held entire kernel) ----
    const int a_row = lane & 15;
    const int a_kb  = (lane >> 4) * 16;
    uint32_t qhi[4][4], qlo[4][4];
#pragma unroll
    for (int ks = 0; ks < 4; ks++) {
        const uint32_t ro = (uint32_t)((w * 16 + a_row) * (KST * 2) + ks * 32 + a_kb);
        ldsm_x4(qhi[ks], sb_b + ro);
        ldsm_x4(qlo[ks], sb_b + 2 * 64 * KST * 2 + ro);
    }

    const int b_row = (lane & 7) + ((lane >> 4) << 3);
    const int b_kb  = ((lane >> 3) & 1) * 16;

    float m0 = -1e30f, m1 = -1e30f, l0 = 0.f, l1 = 0.f;
    float oacc[8][4];
#pragma unroll
    for (int nt = 0; nt < 8; nt++)
#pragma unroll
        for (int r = 0; r < 4; r++) oacc[nt][r] = 0.f;

    for (int k0 = 0; k0 < q0 + 128; k0 += 64) {
        __syncthreads();   // prior iter's smem fully consumed (frags in regs)

        // ---- load K,V tiles [64 x 64] f32 -> hi/lo bf16 smem ----
#pragma unroll
        for (int it = 0; it < 4; it++) {
            const int i  = t + it * 256;     // 0..1023 float4
            const int r  = i >> 4;
            const int c4 = (i & 15) << 2;
            const int eo = r * KST + c4;

            float4 kv = *(const float4*)&Kg[(size_t)(k0 + r) * HD + c4];
            float hx = bf16round(kv.x), hy = bf16round(kv.y);
            float hz = bf16round(kv.z), hw = bf16round(kv.w);
            *(uint2*)&sb[eo] =
                make_uint2(pack2bf16(kv.x, kv.y), pack2bf16(kv.z, kv.w));
            *(uint2*)&sb[64 * KST + eo] =
                make_uint2(pack2bf16(kv.x - hx, kv.y - hy),
                           pack2bf16(kv.z - hz, kv.w - hw));

            float4 vv = *(const float4*)&Vg[(size_t)(k0 + r) * HD + c4];
            hx = bf16round(vv.x); hy = bf16round(vv.y);
            hz = bf16round(vv.z); hw = bf16round(vv.w);
            *(uint2*)&sb[2 * 64 * KST + eo] =
                make_uint2(pack2bf16(vv.x, vv.y), pack2bf16(vv.z, vv.w));
            *(uint2*)&sb[3 * 64 * KST + eo] =
                make_uint2(pack2bf16(vv.x - hx, vv.y - hy),
                           pack2bf16(vv.z - hz, vv.w - hw));
        }
        __syncthreads();

        // ---- S = Q @ K^T (3-term bf16 split) ----
        float sacc[8][4];
#pragma unroll
        for (int nt = 0; nt < 8; nt++)
#pragma unroll
            for (int r = 0; r < 4; r++) sacc[nt][r] = 0.f;

#pragma unroll
        for (int ks = 0; ks < 4; ks++) {
            uint32_t kh[4][4], kl[4][4];
#pragma unroll
            for (int g = 0; g < 4; g++) {
                const uint32_t ro =
                    (uint32_t)((g * 16 + b_row) * (KST * 2) + ks * 32 + b_kb);
                ldsm_x4(kh[g], khi_b + ro);
                ldsm_x4(kl[g], klo_b + ro);
            }
#pragma unroll
            for (int nt = 0; nt < 8; nt++) {
                const int g  = nt >> 1;
                const int hf = (nt & 1) * 2;
                mma_bf16(sacc[nt], qhi[ks], kh[g][hf], kh[g][hf + 1]);
                mma_bf16(sacc[nt], qhi[ks], kl[g][hf], kl[g][hf + 1]);
                mma_bf16(sacc[nt], qlo[ks], kh[g][hf], kh[g][hf + 1]);
            }
        }

        // ---- causal mask (only tiles crossing/above the diagonal) ----
        if (k0 >= q0) {
            const int grow = q0 + w * 16 + (lane >> 2);
#pragma unroll
            for (int nt = 0; nt < 8; nt++) {
                const int gc = k0 + nt * 8 + (lane & 3) * 2;
                if (gc     > grow)     sacc[nt][0] = -1e30f;
                if (gc + 1 > grow)     sacc[nt][1] = -1e30f;
                if (gc     > grow + 8) sacc[nt][2] = -1e30f;
                if (gc + 1 > grow + 8) sacc[nt][3] = -1e30f;
            }
        }

        // ---- online softmax (rows lane>>2 and lane>>2 + 8) ----
        float mx0 = -1e30f, mx1 = -1e30f;
#pragma unroll
        for (int nt = 0; nt < 8; nt++) {
            mx0 = fmaxf(mx0, fmaxf(sacc[nt][0], sacc[nt][1]));
            mx1 = fmaxf(mx1, fmaxf(sacc[nt][2], sacc[nt][3]));
        }
        mx0 = fmaxf(mx0, __shfl_xor_sync(0xffffffffu, mx0, 1));
        mx0 = fmaxf(mx0, __shfl_xor_sync(0xffffffffu, mx0, 2));
        mx1 = fmaxf(mx1, __shfl_xor_sync(0xffffffffu, mx1, 1));
        mx1 = fmaxf(mx1, __shfl_xor_sync(0xffffffffu, mx1, 2));

        const float mn0 = fmaxf(m0, mx0);
        const float mn1 = fmaxf(m1, mx1);
        float sum0 = 0.f, sum1 = 0.f;
#pragma unroll
        for (int nt = 0; nt < 8; nt++) {
            sacc[nt][0] = __expf(sacc[nt][0] - mn0); sum0 += sacc[nt][0];
            sacc[nt][1] = __expf(sacc[nt][1] - mn0); sum0 += sacc[nt][1];
            sacc[nt][2] = __expf(sacc[nt][2] - mn1); sum1 += sacc[nt][2];
            sacc[nt][3] = __expf(sacc[nt][3] - mn1); sum1 += sacc[nt][3];
        }
        sum0 += __shfl_xor_sync(0xffffffffu, sum0, 1);
        sum0 += __shfl_xor_sync(0xffffffffu, sum0, 2);
        sum1 += __shfl_xor_sync(0xffffffffu, sum1, 1);
        sum1 += __shfl_xor_sync(0xffffffffu, sum1, 2);

        const float sc0 = __expf(m0 - mn0);
        const float sc1 = __expf(m1 - mn1);
        l0 = l0 * sc0 + sum0; m0 = mn0;
        l1 = l1 * sc1 + sum1; m1 = mn1;
#pragma unroll
        for (int nt = 0; nt < 8; nt++) {
            oacc[nt][0] *= sc0; oacc[nt][1] *= sc0;
            oacc[nt][2] *= sc1; oacc[nt][3] *= sc1;
        }

        // ---- O += P @ V  (P frags built in registers; V via ldmatrix.trans) ----
#pragma unroll
        for (int ks = 0; ks < 4; ks++) {
            uint32_t ph[4], pl[4];
            {
                const float p00 = sacc[2 * ks][0],     p01 = sacc[2 * ks][1];
                const float p02 = sacc[2 * ks][2],     p03 = sacc[2 * ks][3];
                const float p10 = sacc[2 * ks + 1][0], p11 = sacc[2 * ks + 1][1];
                const float p12 = sacc[2 * ks + 1][2], p13 = sacc[2 * ks + 1][3];
                ph[0] = pack2bf16(p00, p01);
                ph[1] = pack2bf16(p02, p03);
                ph[2] = pack2bf16(p10, p11);
                ph[3] = pack2bf16(p12, p13);
                pl[0] = pack2bf16(p00 - bf16round(p00), p01 - bf16round(p01));
                pl[1] = pack2bf16(p02 - bf16round(p02), p03 - bf16round(p03));
                pl[2] = pack2bf16(p10 - bf16round(p10), p11 - bf16round(p11));
                pl[3] = pack2bf16(p12 - bf16round(p12), p13 - bf16round(p13));
            }
            uint32_t vh[4][4], vl[4][4];
#pragma unroll
            for (int g = 0; g < 4; g++) {
                const uint32_t ro =
                    (uint32_t)((ks * 16 + a_row) * (KST * 2) + g * 32 + a_kb);
                ldsm_x4_t(vh[g], vhi_b + ro);
                ldsm_x4_t(vl[g], vlo_b + ro);
            }
#pragma unroll
            for (int nt = 0; nt < 8; nt++) {
                const int g  = nt >> 1;
                const int hf = (nt & 1) * 2;
                mma_bf16(oacc[nt], ph, vh[g][hf], vh[g][hf + 1]);
                mma_bf16(oacc[nt], ph, vl[g][hf], vl[g][hf + 1]);
                mma_bf16(oacc[nt], pl, vh[g][hf], vh[g][hf + 1]);
            }
        }
    }

    // ---- finalize + write to g_attn [B,S,HID] ----
    const float il0 = 1.f / l0;
    const float il1 = 1.f / l1;
    const int r0 = q0 + w * 16 + (lane >> 2);
#pragma unroll
    for (int nt = 0; nt < 8; nt++) {
        const int d = nt * 8 + (lane & 3) * 2;
        float2 v0, v1;
        v0.x = oacc[nt][0] * il0; v0.y = oacc[nt][1] * il0;
        v1.x = oacc[nt][2] * il1; v1.y = oacc[nt][3] * il1;
        *(float2*)&g_attn[((size_t)bb * S + r0) * HID + hh * 64 + d]     = v0;
        *(float2*)&g_attn[((size_t)bb * S + r0 + 8) * HID + hh * 64 + d] = v1;
    }
}

// ---------------------------------------------------------------------------
// Launch: 3 QKV GEMMs -> attention -> output GEMM
// ---------------------------------------------------------------------------
extern "C" void kernel_launch(void* const* d_in, const int* in_sizes, int n_in,
                              void* d_out, int out_size)
{
    const float* x  = (const float*)d_in[0];
    const float* Wq = (const float*)d_in[1];
    const float* bq = (const float*)d_in[2];
    const float* Wk = (const float*)d_in[3];
    const float* bk = (const float*)d_in[4];
    const float* Wv = (const float*)d_in[5];
    const float* bv = (const float*)d_in[6];
    const float* Wo = (const float*)d_in[7];
    const float* bo = (const float*)d_in[8];
    float* out = (float*)d_out;

    dim3 gg(HID / 128, M / 128);   // (8, 32)
    gemm_mma_kernel<0><<<gg, 256>>>(x, Wq, bq, nullptr);
    gemm_mma_kernel<1><<<gg, 256>>>(x, Wk, bk, nullptr);
    gemm_mma_kernel<2><<<gg, 256>>>(x, Wv, bv, nullptr);

    attn_mma_kernel<<<dim3(S / 128, B * NH), 256>>>();

    gemm_mma_kernel<3><<<gg, 256>>>(nullptr, Wo, bo, out);
}

// round 7
// speedup vs baseline: 2.6478x; 1.0089x over previous
#include <cuda_runtime.h>
#include <cuda_bf16.h>
#include <cstdint>

// Problem constants
constexpr int HID = 1024;
constexpr int NH  = 16;
constexpr int HD  = 64;     // head dim
constexpr int B   = 2;
constexpr int S   = 2048;
constexpr int M   = B * S;  // 4096 rows for projection GEMMs

// ---------------------------------------------------------------------------
// Scratch (__device__ globals; allocation-free rule)
// ---------------------------------------------------------------------------
__device__ __nv_bfloat16 g_xhi[(size_t)M * HID];
__device__ __nv_bfloat16 g_xlo[(size_t)M * HID];
__device__ __nv_bfloat16 g_whi[(size_t)4 * HID * HID];
__device__ __nv_bfloat16 g_wlo[(size_t)4 * HID * HID];
// q/k/v in [B,H,S,D] layout, bf16 hi/lo (q pre-scaled by 0.125)
__device__ __nv_bfloat16 g_qhi[(size_t)M * HID];
__device__ __nv_bfloat16 g_qlo[(size_t)M * HID];
__device__ __nv_bfloat16 g_khi[(size_t)M * HID];
__device__ __nv_bfloat16 g_klo[(size_t)M * HID];
__device__ __nv_bfloat16 g_vhi[(size_t)M * HID];
__device__ __nv_bfloat16 g_vlo[(size_t)M * HID];
// attention output [B,S,HID], bf16 hi/lo (A operand of the O-projection)
__device__ __nv_bfloat16 g_ahi[(size_t)M * HID];
__device__ __nv_bfloat16 g_alo[(size_t)M * HID];

// ---------------------------------------------------------------------------
// PTX helpers
// ---------------------------------------------------------------------------
__device__ __forceinline__ uint32_t smem_u32(const void* p) {
    uint32_t a;
    asm("{ .reg .u64 t; cvta.to.shared.u64 t, %1; cvt.u32.u64 %0, t; }"
        : "=r"(a) : "l"(p));
    return a;
}

__device__ __forceinline__ void ldsm_x4(uint32_t (&r)[4], uint32_t addr) {
    asm volatile("ldmatrix.sync.aligned.m8n8.x4.shared.b16 {%0,%1,%2,%3}, [%4];"
                 : "=r"(r[0]), "=r"(r[1]), "=r"(r[2]), "=r"(r[3]) : "r"(addr));
}

__device__ __forceinline__ void ldsm_x4_t(uint32_t (&r)[4], uint32_t addr) {
    asm volatile("ldmatrix.sync.aligned.m8n8.x4.trans.shared.b16 {%0,%1,%2,%3}, [%4];"
                 : "=r"(r[0]), "=r"(r[1]), "=r"(r[2]), "=r"(r[3]) : "r"(addr));
}

__device__ __forceinline__ void mma_bf16(float (&d)[4], const uint32_t (&a)[4],
                                         uint32_t b0, uint32_t b1) {
    asm volatile(
        "mma.sync.aligned.m16n8k16.row.col.f32.bf16.bf16.f32 "
        "{%0,%1,%2,%3}, {%4,%5,%6,%7}, {%8,%9}, {%0,%1,%2,%3};"
        : "+f"(d[0]), "+f"(d[1]), "+f"(d[2]), "+f"(d[3])
        : "r"(a[0]), "r"(a[1]), "r"(a[2]), "r"(a[3]), "r"(b0), "r"(b1));
}

__device__ __forceinline__ void cp16(uint32_t dst, const void* src) {
    asm volatile("cp.async.cg.shared.global [%0], [%1], 16;"
                 :: "r"(dst), "l"(src));
}
#define CP_COMMIT() asm volatile("cp.async.commit_group;")
#define CP_WAIT0()  asm volatile("cp.async.wait_group 0;")
#define CP_WAIT1()  asm volatile("cp.async.wait_group 1;")

__device__ __forceinline__ uint32_t pack2bf16(float a, float b) {
    __nv_bfloat162 h = __floats2bfloat162_rn(a, b);
    return *reinterpret_cast<uint32_t*>(&h);
}

__device__ __forceinline__ float bf16round(float x) {
    return __bfloat162float(__float2bfloat16(x));
}

// ---------------------------------------------------------------------------
// Pre-pass: split f32 -> bf16 (hi, lo).  sel: 0 = x, 1..4 = W[sel-1]
// ---------------------------------------------------------------------------
__global__ __launch_bounds__(256)
void cvt_kernel(const float* __restrict__ src, int sel)
{
    __nv_bfloat16 *hi, *lo;
    if (sel == 0) { hi = g_xhi; lo = g_xlo; }
    else {
        hi = g_whi + (size_t)(sel - 1) * HID * HID;
        lo = g_wlo + (size_t)(sel - 1) * HID * HID;
    }
    const int i = blockIdx.x * 256 + threadIdx.x;   // float4 index
    float4 v = ((const float4*)src)[i];
    const float hx = bf16round(v.x), hy = bf16round(v.y);
    const float hz = bf16round(v.z), hw = bf16round(v.w);
    ((uint2*)hi)[i] = make_uint2(pack2bf16(v.x, v.y), pack2bf16(v.z, v.w));
    ((uint2*)lo)[i] = make_uint2(pack2bf16(v.x - hx, v.y - hy),
                                 pack2bf16(v.z - hz, v.w - hw));
}

// ---------------------------------------------------------------------------
// GEMM v2: C = A @ W^T + bias, operands pre-split bf16 hi/lo in global.
// 128x128 tile, BK=32, 256 threads, cp.async 2-stage pipeline.
//   DEST 0/1/2: scatter to g_{q,k,v}{hi,lo} [B,H,S,D] (DEST 0 scaled 0.125)
//   DEST 3:     A = g_a{hi,lo}; write f32 [M,HID] to Cout
// ---------------------------------------------------------------------------
constexpr int AST = 40;                      // padded bf16 row stride (80 B)
constexpr int G_TILE  = 128 * AST * 2;       // 10240 B per tile
constexpr int G_STAGE = 4 * G_TILE;          // 40960 B per stage
constexpr int G_SMEM  = 2 * G_STAGE;         // 81920 B

template <int DEST>
__global__ __launch_bounds__(256, 2)
void gemm_mma_kernel(const float* __restrict__ bias,
                     float* __restrict__ Cout)
{
    extern __shared__ char dynsm[];
    const uint32_t smb = smem_u32(dynsm);

    const __nv_bfloat16* Ahi_g = (DEST == 3) ? g_ahi : g_xhi;
    const __nv_bfloat16* Alo_g = (DEST == 3) ? g_alo : g_xlo;
    const __nv_bfloat16* Whi_g = g_whi + (size_t)DEST * HID * HID;
    const __nv_bfloat16* Wlo_g = g_wlo + (size_t)DEST * HID * HID;

    const int t      = threadIdx.x;
    const int lane   = t & 31;
    const int wid    = t >> 5;
    const int warp_m = wid >> 2;
    const int warp_n = wid & 3;
    const int m0 = blockIdx.y * 128;
    const int n0 = blockIdx.x * 128;

    const int a_row = lane & 15;
    const int a_kb  = (lane >> 4) * 16;
    const int b_row = (lane & 7) + ((lane >> 4) << 3);
    const int b_kb  = ((lane >> 3) & 1) * 16;

    // per-thread load coords: 512 16B-chunks per array per chunk; 2 per thread
    const int lr0 = t >> 2;            // rows for it=0 : 0..63
    const int lj  = (t & 3);           // chunk 0..3 (16B = 8 bf16)

    auto load_chunk = [&](int stage, int k0) {
#pragma unroll
        for (int it = 0; it < 2; it++) {
            const int r = lr0 + it * 64;
            const size_t aoff = (size_t)(m0 + r) * HID + k0 + lj * 8;
            const size_t woff = (size_t)(n0 + r) * HID + k0 + lj * 8;
            const uint32_t d = smb + stage * G_STAGE + r * 80 + lj * 16;
            cp16(d,              Ahi_g + aoff);
            cp16(d + G_TILE,     Alo_g + aoff);
            cp16(d + 2 * G_TILE, Whi_g + woff);
            cp16(d + 3 * G_TILE, Wlo_g + woff);
        }
    };

    float acc[4][4][4];
#pragma unroll
    for (int mt = 0; mt < 4; mt++)
#pragma unroll
        for (int nt = 0; nt < 4; nt++)
#pragma unroll
            for (int r = 0; r < 4; r++) acc[mt][nt][r] = 0.f;

    load_chunk(0, 0);
    CP_COMMIT();

    for (int c = 0; c < 32; c++) {
        if (c + 1 < 32) {
            load_chunk((c + 1) & 1, (c + 1) * 32);
            CP_COMMIT();
            CP_WAIT1();
        } else {
            CP_WAIT0();
        }
        __syncthreads();

        const uint32_t sb = smb + (c & 1) * G_STAGE;
#pragma unroll
        for (int ks = 0; ks < 2; ks++) {
            const int ksb = ks * 32;

            uint32_t a_hi[4][4], a_lo[4][4];
#pragma unroll
            for (int mt = 0; mt < 4; mt++) {
                const uint32_t ro =
                    (uint32_t)((warp_m * 64 + mt * 16 + a_row) * 80 + ksb + a_kb);
                ldsm_x4(a_hi[mt], sb + ro);
                ldsm_x4(a_lo[mt], sb + G_TILE + ro);
            }
            uint32_t b_hi[2][4], b_lo[2][4];
#pragma unroll
            for (int bt = 0; bt < 2; bt++) {
                const uint32_t ro =
                    (uint32_t)((warp_n * 32 + bt * 16 + b_row) * 80 + ksb + b_kb);
                ldsm_x4(b_hi[bt], sb + 2 * G_TILE + ro);
                ldsm_x4(b_lo[bt], sb + 3 * G_TILE + ro);
            }

#pragma unroll
            for (int mt = 0; mt < 4; mt++)
#pragma unroll
                for (int nt = 0; nt < 4; nt++) {
                    const int bt = nt >> 1;
                    const int hf = (nt & 1) * 2;
                    mma_bf16(acc[mt][nt], a_hi[mt], b_hi[bt][hf], b_hi[bt][hf + 1]);
                    mma_bf16(acc[mt][nt], a_hi[mt], b_lo[bt][hf], b_lo[bt][hf + 1]);
                    mma_bf16(acc[mt][nt], a_lo[mt], b_hi[bt][hf], b_hi[bt][hf + 1]);
                }
        }
        __syncthreads();
    }

    // ---- epilogue ----
    const int fr = lane >> 2;
    const int fc = (lane & 3) * 2;
    const float scl = (DEST == 0) ? 0.125f : 1.f;
#pragma unroll
    for (int mt = 0; mt < 4; mt++)
#pragma unroll
        for (int nt = 0; nt < 4; nt++) {
            const int n = n0 + warp_n * 32 + nt * 8 + fc;
            const float2 b2 = *(const float2*)&bias[n];
#pragma unroll
            for (int p = 0; p < 2; p++) {
                const int m = m0 + warp_m * 64 + mt * 16 + fr + p * 8;
                float vx = (acc[mt][nt][p * 2 + 0] + b2.x) * scl;
                float vy = (acc[mt][nt][p * 2 + 1] + b2.y) * scl;
                if (DEST < 3) {
                    const int bb = m >> 11;
                    const int ss = m & (S - 1);
                    const int hh = n >> 6;
                    const int dd = n & 63;
                    const size_t idx =
                        (((size_t)(bb * NH + hh) * S + ss) << 6) + dd;
                    __nv_bfloat16* Chi = (DEST == 0) ? g_qhi
                                       : (DEST == 1) ? g_khi : g_vhi;
                    __nv_bfloat16* Clo = (DEST == 0) ? g_qlo
                                       : (DEST == 1) ? g_klo : g_vlo;
                    *(uint32_t*)&Chi[idx] = pack2bf16(vx, vy);
                    *(uint32_t*)&Clo[idx] =
                        pack2bf16(vx - bf16round(vx), vy - bf16round(vy));
                } else {
                    float2 v; v.x = vx; v.y = vy;
                    *(float2*)&Cout[(size_t)m * HID + n] = v;
                }
            }
        }
}

// ---------------------------------------------------------------------------
// Tensor-core causal flash attention, pre-split bf16 inputs, cp.async
// 2-stage pipeline. CTA: 128 q rows, 8 warps; K/V tiles of 64 keys.
// KST=72 (144 B rows): 16B-aligned, conflict-free ldmatrix.
// ---------------------------------------------------------------------------
constexpr int KST     = 72;
constexpr int A_TILE  = 64 * KST * 2;     // 9216 B
constexpr int A_STAGE = 4 * A_TILE;       // 36864 B (Khi|Klo|Vhi|Vlo)
constexpr int A_SMEM  = 2 * A_STAGE;      // 73728 B

__global__ __launch_bounds__(256)
void attn_mma_kernel()
{
    extern __shared__ char dynsm[];
    const uint32_t smb = smem_u32(dynsm);

    const int t    = threadIdx.x;
    const int lane = t & 31;
    const int w    = t >> 5;
    const int q0   = (gridDim.x - 1 - blockIdx.x) * 128;  // longest first
    const int bh   = blockIdx.y;
    const int bb   = bh >> 4;
    const int hh   = bh & 15;

    const size_t bh_off = (size_t)bh * S * HD;
    const __nv_bfloat16* Khi_g = g_khi + bh_off;
    const __nv_bfloat16* Klo_g = g_klo + bh_off;
    const __nv_bfloat16* Vhi_g = g_vhi + bh_off;
    const __nv_bfloat16* Vlo_g = g_vlo + bh_off;

    // ---- stage Q via cp.async into stage0, pull fragments to registers ----
    {
#pragma unroll
        for (int it = 0; it < 4; it++) {
            const int i = t + it * 256;      // 0..1023
            const int r = i >> 3;            // 0..127
            const int j = i & 7;
            const size_t off = bh_off + (size_t)(q0 + r) * HD + j * 8;
            const uint32_t d = smb + r * 144 + j * 16;
            cp16(d,                 g_qhi + off);
            cp16(d + 128 * 144,     g_qlo + off);
        }
        CP_COMMIT();
        CP_WAIT0();
        __syncthreads();
    }

    const int a_row = lane & 15;
    const int a_kb  = (lane >> 4) * 16;
    uint32_t qhi[4][4], qlo[4][4];
#pragma unroll
    for (int ks = 0; ks < 4; ks++) {
        const uint32_t ro = (uint32_t)((w * 16 + a_row) * 144 + ks * 32 + a_kb);
        ldsm_x4(qhi[ks], smb + ro);
        ldsm_x4(qlo[ks], smb + 128 * 144 + ro);
    }
    __syncthreads();   // all warps done reading Q before stage0 is reused

    const int b_row = (lane & 7) + ((lane >> 4) << 3);
    const int b_kb  = ((lane >> 3) & 1) * 16;

    // per-thread tile-load coords (512 chunks/array/tile, 2 per thread)
    const int lr0 = t >> 2;          // 0..63 over 2 its? no: 64 rows x 8 chunks
    auto load_tile = [&](int stage, int k0) {
#pragma unroll
        for (int it = 0; it < 2; it++) {
            const int i = t + it * 256;   // 0..511
            const int r = i >> 3;         // 0..63
            const int j = i & 7;
            const size_t off = (size_t)(k0 + r) * HD + j * 8;
            const uint32_t d = smb + stage * A_STAGE + r * 144 + j * 16;
            cp16(d,              Khi_g + off);
            cp16(d + A_TILE,     Klo_g + off);
            cp16(d + 2 * A_TILE, Vhi_g + off);
            cp16(d + 3 * A_TILE, Vlo_g + off);
        }
    };
    (void)lr0;

    float m0 = -1e30f, m1 = -1e30f, l0 = 0.f, l1 = 0.f;
    float oacc[8][4];
#pragma unroll
    for (int nt = 0; nt < 8; nt++)
#pragma unroll
        for (int r = 0; r < 4; r++) oacc[nt][r] = 0.f;

    const int nk = q0 / 64 + 2;
    load_tile(0, 0);
    CP_COMMIT();

    for (int ki = 0; ki < nk; ki++) {
        const int k0 = ki * 64;
        if (ki + 1 < nk) {
            load_tile((ki + 1) & 1, k0 + 64);
            CP_COMMIT();
            CP_WAIT1();
        } else {
            CP_WAIT0();
        }
        __syncthreads();

        const uint32_t sb = smb + (ki & 1) * A_STAGE;

        // ---- S = Q @ K^T (3-term bf16 split) ----
        float sacc[8][4];
#pragma unroll
        for (int nt = 0; nt < 8; nt++)
#pragma unroll
            for (int r = 0; r < 4; r++) sacc[nt][r] = 0.f;

#pragma unroll
        for (int ks = 0; ks < 4; ks++) {
            uint32_t kh[4][4], kl[4][4];
#pragma unroll
            for (int g = 0; g < 4; g++) {
                const uint32_t ro =
                    (uint32_t)((g * 16 + b_row) * 144 + ks * 32 + b_kb);
                ldsm_x4(kh[g], sb + ro);
                ldsm_x4(kl[g], sb + A_TILE + ro);
            }
#pragma unroll
            for (int nt = 0; nt < 8; nt++) {
                const int g  = nt >> 1;
                const int hf = (nt & 1) * 2;
                mma_bf16(sacc[nt], qhi[ks], kh[g][hf], kh[g][hf + 1]);
                mma_bf16(sacc[nt], qhi[ks], kl[g][hf], kl[g][hf + 1]);
                mma_bf16(sacc[nt], qlo[ks], kh[g][hf], kh[g][hf + 1]);
            }
        }

        // ---- causal mask ----
        if (k0 >= q0) {
            const int grow = q0 + w * 16 + (lane >> 2);
#pragma unroll
            for (int nt = 0; nt < 8; nt++) {
                const int gc = k0 + nt * 8 + (lane & 3) * 2;
                if (gc     > grow)     sacc[nt][0] = -1e30f;
                if (gc + 1 > grow)     sacc[nt][1] = -1e30f;
                if (gc     > grow + 8) sacc[nt][2] = -1e30f;
                if (gc + 1 > grow + 8) sacc[nt][3] = -1e30f;
            }
        }

        // ---- online softmax ----
        float mx0 = -1e30f, mx1 = -1e30f;
#pragma unroll
        for (int nt = 0; nt < 8; nt++) {
            mx0 = fmaxf(mx0, fmaxf(sacc[nt][0], sacc[nt][1]));
            mx1 = fmaxf(mx1, fmaxf(sacc[nt][2], sacc[nt][3]));
        }
        mx0 = fmaxf(mx0, __shfl_xor_sync(0xffffffffu, mx0, 1));
        mx0 = fmaxf(mx0, __shfl_xor_sync(0xffffffffu, mx0, 2));
        mx1 = fmaxf(mx1, __shfl_xor_sync(0xffffffffu, mx1, 1));
        mx1 = fmaxf(mx1, __shfl_xor_sync(0xffffffffu, mx1, 2));

        const float mn0 = fmaxf(m0, mx0);
        const float mn1 = fmaxf(m1, mx1);
        float sum0 = 0.f, sum1 = 0.f;
#pragma unroll
        for (int nt = 0; nt < 8; nt++) {
            sacc[nt][0] = __expf(sacc[nt][0] - mn0); sum0 += sacc[nt][0];
            sacc[nt][1] = __expf(sacc[nt][1] - mn0); sum0 += sacc[nt][1];
            sacc[nt][2] = __expf(sacc[nt][2] - mn1); sum1 += sacc[nt][2];
            sacc[nt][3] = __expf(sacc[nt][3] - mn1); sum1 += sacc[nt][3];
        }
        sum0 += __shfl_xor_sync(0xffffffffu, sum0, 1);
        sum0 += __shfl_xor_sync(0xffffffffu, sum0, 2);
        sum1 += __shfl_xor_sync(0xffffffffu, sum1, 1);
        sum1 += __shfl_xor_sync(0xffffffffu, sum1, 2);

        const float sc0 = __expf(m0 - mn0);
        const float sc1 = __expf(m1 - mn1);
        l0 = l0 * sc0 + sum0; m0 = mn0;
        l1 = l1 * sc1 + sum1; m1 = mn1;
#pragma unroll
        for (int nt = 0; nt < 8; nt++) {
            oacc[nt][0] *= sc0; oacc[nt][1] *= sc0;
            oacc[nt][2] *= sc1; oacc[nt][3] *= sc1;
        }

        // ---- O += P @ V  (P frags in registers; V via ldmatrix.trans) ----
#pragma unroll
        for (int ks = 0; ks < 4; ks++) {
            uint32_t ph[4], pl[4];
            {
                const float p00 = sacc[2 * ks][0],     p01 = sacc[2 * ks][1];
                const float p02 = sacc[2 * ks][2],     p03 = sacc[2 * ks][3];
                const float p10 = sacc[2 * ks + 1][0], p11 = sacc[2 * ks + 1][1];
                const float p12 = sacc[2 * ks + 1][2], p13 = sacc[2 * ks + 1][3];
                ph[0] = pack2bf16(p00, p01);
                ph[1] = pack2bf16(p02, p03);
                ph[2] = pack2bf16(p10, p11);
                ph[3] = pack2bf16(p12, p13);
                pl[0] = pack2bf16(p00 - bf16round(p00), p01 - bf16round(p01));
                pl[1] = pack2bf16(p02 - bf16round(p02), p03 - bf16round(p03));
                pl[2] = pack2bf16(p10 - bf16round(p10), p11 - bf16round(p11));
                pl[3] = pack2bf16(p12 - bf16round(p12), p13 - bf16round(p13));
            }
            uint32_t vh[4][4], vl[4][4];
#pragma unroll
            for (int g = 0; g < 4; g++) {
                const uint32_t ro =
                    (uint32_t)((ks * 16 + a_row) * 144 + g * 32 + a_kb);
                ldsm_x4_t(vh[g], sb + 2 * A_TILE + ro);
                ldsm_x4_t(vl[g], sb + 3 * A_TILE + ro);
            }
#pragma unroll
            for (int nt = 0; nt < 8; nt++) {
                const int g  = nt >> 1;
                const int hf = (nt & 1) * 2;
                mma_bf16(oacc[nt], ph, vh[g][hf], vh[g][hf + 1]);
                mma_bf16(oacc[nt], ph, vl[g][hf], vl[g][hf + 1]);
                mma_bf16(oacc[nt], pl, vh[g][hf], vh[g][hf + 1]);
            }
        }
        __syncthreads();   // compute done before next iter overwrites buffer
    }

    // ---- finalize + write bf16 hi/lo to g_a{hi,lo} [B,S,HID] ----
    const float il0 = 1.f / l0;
    const float il1 = 1.f / l1;
    const int r0 = q0 + w * 16 + (lane >> 2);
#pragma unroll
    for (int nt = 0; nt < 8; nt++) {
        const int d = nt * 8 + (lane & 3) * 2;
        const float v0x = oacc[nt][0] * il0, v0y = oacc[nt][1] * il0;
        const float v1x = oacc[nt][2] * il1, v1y = oacc[nt][3] * il1;
        const size_t i0 = ((size_t)bb * S + r0) * HID + hh * 64 + d;
        const size_t i1 = ((size_t)bb * S + r0 + 8) * HID + hh * 64 + d;
        *(uint32_t*)&g_ahi[i0] = pack2bf16(v0x, v0y);
        *(uint32_t*)&g_alo[i0] =
            pack2bf16(v0x - bf16round(v0x), v0y - bf16round(v0y));
        *(uint32_t*)&g_ahi[i1] = pack2bf16(v1x, v1y);
        *(uint32_t*)&g_alo[i1] =
            pack2bf16(v1x - bf16round(v1x), v1y - bf16round(v1y));
    }
}

// ---------------------------------------------------------------------------
// Launch: convert pre-pass -> 3 QKV GEMMs -> attention -> output GEMM
// ---------------------------------------------------------------------------
extern "C" void kernel_launch(void* const* d_in, const int* in_sizes, int n_in,
                              void* d_out, int out_size)
{
    const float* x  = (const float*)d_in[0];
    const float* Wq = (const float*)d_in[1];
    const float* bq = (const float*)d_in[2];
    const float* Wk = (const float*)d_in[3];
    const float* bk = (const float*)d_in[4];
    const float* Wv = (const float*)d_in[5];
    const float* bv = (const float*)d_in[6];
    const float* Wo = (const float*)d_in[7];
    const float* bo = (const float*)d_in[8];
    float* out = (float*)d_out;

    cudaFuncSetAttribute(attn_mma_kernel,
                         cudaFuncAttributeMaxDynamicSharedMemorySize, A_SMEM);
    cudaFuncSetAttribute(gemm_mma_kernel<0>,
                         cudaFuncAttributeMaxDynamicSharedMemorySize, G_SMEM);
    cudaFuncSetAttribute(gemm_mma_kernel<1>,
                         cudaFuncAttributeMaxDynamicSharedMemorySize, G_SMEM);
    cudaFuncSetAttribute(gemm_mma_kernel<2>,
                         cudaFuncAttributeMaxDynamicSharedMemorySize, G_SMEM);
    cudaFuncSetAttribute(gemm_mma_kernel<3>,
                         cudaFuncAttributeMaxDynamicSharedMemorySize, G_SMEM);

    // pre-pass: x (4M elems -> 1M float4), each W (1M elems -> 256K float4)
    cvt_kernel<<<(M * HID / 4) / 256, 256>>>(x, 0);
    cvt_kernel<<<(HID * HID / 4) / 256, 256>>>(Wq, 1);
    cvt_kernel<<<(HID * HID / 4) / 256, 256>>>(Wk, 2);
    cvt_kernel<<<(HID * HID / 4) / 256, 256>>>(Wv, 3);
    cvt_kernel<<<(HID * HID / 4) / 256, 256>>>(Wo, 4);

    dim3 gg(HID / 128, M / 128);   // (8, 32)
    gemm_mma_kernel<0><<<gg, 256, G_SMEM>>>(bq, nullptr);
    gemm_mma_kernel<1><<<gg, 256, G_SMEM>>>(bk, nullptr);
    gemm_mma_kernel<2><<<gg, 256, G_SMEM>>>(bv, nullptr);

    attn_mma_kernel<<<dim3(S / 128, B * NH), 256, A_SMEM>>>();

    gemm_mma_kernel<3><<<gg, 256, G_SMEM>>>(bo, out);
}